// round 6
// baseline (speedup 1.0000x reference)
#include <cuda_runtime.h>
#include <cuda_bf16.h>
#include <math.h>
#include <stdint.h>

// ConvEncoder: y = GELU(im2col(emb[x]) @ W^T + b).  M=32768, N=128, K=640.
// mma.sync m16n8k16 bf16, split precision: D += AhWh + AhWl + AlWh (~2^-17 err).
// R6: 2 CTAs/SM (128 tok, 256 thr) so prologue gather / GELU epilogue of one
// CTA overlaps the tensor mainloop of its SM-mate. W streamed as K=32
// sub-chunks in a 2-deep cp.async ring to fit 113.3 KB smem/CTA.

#define CE_S    2048
#define CE_KTOT 640
#define THREADS 256
#define TOK     128
#define ROW_B   272                  // A smem row stride
#define WROW    80                   // W smem row stride (64B data + 16B pad)

// smem layout (bytes)
#define SA_HI   0
#define SA_LO   35904                // 132 * 272
#define SW_BASE 71808                // ring: 2 stages x (hi 10240 + lo 10240)
#define SW_STG  20480
#define SW_LO   10240
#define SBIAS   112768
#define SM_TOT  113280

// W pre-converted: [h(2)][kc(5)][o(128)][272B]
__device__ __align__(16) unsigned char g_Wcvt[2 * 5 * 128 * ROW_B];

__device__ __forceinline__ float gelu_exact(float y) {
    return 0.5f * y * (1.0f + erff(y * 0.70710678118654752f));
}

__device__ __forceinline__ void mma_bf16(float* c, const uint32_t* a, const uint32_t* b) {
    asm volatile(
        "mma.sync.aligned.m16n8k16.row.col.f32.bf16.bf16.f32 "
        "{%0,%1,%2,%3}, {%4,%5,%6,%7}, {%8,%9}, {%0,%1,%2,%3};"
        : "+f"(c[0]), "+f"(c[1]), "+f"(c[2]), "+f"(c[3])
        : "r"(a[0]), "r"(a[1]), "r"(a[2]), "r"(a[3]), "r"(b[0]), "r"(b[1]));
}

__device__ __forceinline__ void ldsm4(uint32_t* r, uint32_t addr) {
    asm volatile("ldmatrix.sync.aligned.m8n8.x4.shared.b16 {%0,%1,%2,%3}, [%4];"
                 : "=r"(r[0]), "=r"(r[1]), "=r"(r[2]), "=r"(r[3]) : "r"(addr));
}

__device__ __forceinline__ void ldsm2(uint32_t* r, uint32_t addr) {
    asm volatile("ldmatrix.sync.aligned.m8n8.x2.shared.b16 {%0,%1}, [%2];"
                 : "=r"(r[0]), "=r"(r[1]) : "r"(addr));
}

__device__ __forceinline__ void cpasync16(uint32_t dst, const void* src) {
    asm volatile("cp.async.cg.shared.global [%0], [%1], 16;"
                 :: "r"(dst), "l"(src) : "memory");
}

__device__ __forceinline__ void split4(float4 v, uint2* hi, uint2* lo) {
    union { __nv_bfloat16 h[4]; uint2 u; } ph, pl;
    float f[4] = {v.x, v.y, v.z, v.w};
    #pragma unroll
    for (int j = 0; j < 4; ++j) {
        __nv_bfloat16 hb = __float2bfloat16(f[j]);
        ph.h[j] = hb;
        pl.h[j] = __float2bfloat16(f[j] - __bfloat162float(hb));
    }
    *hi = ph.u;
    *lo = pl.u;
}

// ---- prep: W f32 -> bf16 hi/lo, chunked layout for direct cp.async ----
__global__ void __launch_bounds__(256)
prep_w_kernel(const float* __restrict__ W)
{
    int t = blockIdx.x * 256 + threadIdx.x;        // 5*128*16 = 10240 granules
    if (t >= 5 * 128 * 16) return;
    int gnl = t & 15;
    int o   = (t >> 4) & 127;
    int kc  = t >> 11;
    const float* src = W + (size_t)o * CE_KTOT + kc * 128 + gnl * 8;
    float4 v0 = *reinterpret_cast<const float4*>(src);
    float4 v1 = *reinterpret_cast<const float4*>(src + 4);
    uint2 h0, l0, h1, l1;
    split4(v0, &h0, &l0);
    split4(v1, &h1, &l1);
    size_t off_hi = ((size_t)(0 * 5 + kc) * 128 + o) * ROW_B + gnl * 16;
    size_t off_lo = ((size_t)(1 * 5 + kc) * 128 + o) * ROW_B + gnl * 16;
    *reinterpret_cast<uint4*>(g_Wcvt + off_hi) = make_uint4(h0.x, h0.y, h1.x, h1.y);
    *reinterpret_cast<uint4*>(g_Wcvt + off_lo) = make_uint4(l0.x, l0.y, l1.x, l1.y);
}

// stage one K=32 sub-chunk (hi+lo) into smem ring slot via cp.async
__device__ __forceinline__ void stage_w(uint32_t swdst, int s, int tid) {
    const int kc  = s >> 2;
    const int q32 = s & 3;
    const unsigned char* bh = g_Wcvt + (size_t)(0 * 5 + kc) * 128 * ROW_B;
    const unsigned char* bl = g_Wcvt + (size_t)(1 * 5 + kc) * 128 * ROW_B;
    #pragma unroll
    for (int it = 0; it < 2; ++it) {
        int idx = tid + it * THREADS;              // 512: 128 o x 4 granules
        int o = idx >> 2, gnl = idx & 3;
        uint32_t d = swdst + o * WROW + gnl * 16;
        size_t so = (size_t)o * ROW_B + q32 * 64 + gnl * 16;
        cpasync16(d, bh + so);
        cpasync16(d + SW_LO, bl + so);
    }
}

__global__ void __launch_bounds__(THREADS, 2)
conv_encoder_hmma(const int* __restrict__ x,
                  const float* __restrict__ emb,
                  const float* __restrict__ bias,
                  float* __restrict__ out)
{
    extern __shared__ uint8_t smem[];
    uint32_t sb;
    asm("{ .reg .u64 t; cvta.to.shared.u64 t, %1; cvt.u32.u64 %0, t; }"
        : "=r"(sb) : "l"(smem));

    const int tid = threadIdx.x;
    const int wid = tid >> 5;
    const int lid = tid & 31;
    const int g   = lid >> 2;
    const int q   = lid & 3;
    const int wm  = wid >> 2;       // 0..1  (64-row band)
    const int wn  = wid & 3;        // 0..3  (32-col band)
    const int batch = blockIdx.y;
    const int s0 = blockIdx.x * TOK;
    const int* xrow = x + batch * CE_S;

    // prefetch first two W sub-chunks (overlap with A gather)
    stage_w(sb + SW_BASE, 0, tid);
    asm volatile("cp.async.commit_group;" ::: "memory");
    stage_w(sb + SW_BASE + SW_STG, 1, tid);
    asm volatile("cp.async.commit_group;" ::: "memory");

    if (tid < 32) {
        reinterpret_cast<float4*>(smem + SBIAS)[tid] =
            reinterpret_cast<const float4*>(bias)[tid];
    }

    // ---- stage halo'd A once: rows p=0..131 -> seq s0+p-2, bf16 hi/lo ----
    #pragma unroll
    for (int it = 0; it < 17; ++it) {
        int idx = tid + it * THREADS;              // 132*32 = 4224 float4 tasks
        if (idx < 132 * 32) {
            int p = idx >> 5;
            int c = idx & 31;
            int s = s0 + p - 2;
            float4 v = make_float4(0.f, 0.f, 0.f, 0.f);
            if (s >= 0 && s < CE_S)
                v = *reinterpret_cast<const float4*>(emb + (size_t)xrow[s] * 128 + c * 4);
            uint2 hi, lo;
            split4(v, &hi, &lo);
            *reinterpret_cast<uint2*>(smem + SA_HI + p * ROW_B + c * 8) = hi;
            *reinterpret_cast<uint2*>(smem + SA_LO + p * ROW_B + c * 8) = lo;
        }
    }

    float acc[4][4][4];
    #pragma unroll
    for (int i = 0; i < 4; ++i)
        #pragma unroll
        for (int j = 0; j < 4; ++j)
            #pragma unroll
            for (int r = 0; r < 4; ++r)
                acc[i][j][r] = 0.f;

    // per-lane ldmatrix offsets
    const uint32_t a_off = ((lid & 7) + ((lid >> 3) & 1) * 8) * ROW_B + (lid >> 4) * 16;
    const uint32_t b_off = (lid & 7) * WROW + ((lid >> 3) & 1) * 16;

    // ---- 20 sub-chunks of K=32, 2-deep ring ----
    for (int s = 0; s < 20; ++s) {
        if (s < 19) {
            asm volatile("cp.async.wait_group 1;" ::: "memory");
        } else {
            asm volatile("cp.async.wait_group 0;" ::: "memory");
        }
        __syncthreads();

        const int kc  = s >> 2;
        const int q32 = s & 3;
        const uint32_t swb = sb + SW_BASE + (s & 1) * SW_STG;
        const uint32_t aA  = sb + (wm * 64 + kc) * ROW_B + a_off + q32 * 64;
        const uint32_t aB  = swb + wn * 32 * WROW + b_off;

        #pragma unroll
        for (int ks = 0; ks < 2; ++ks) {
            const uint32_t kb = ks * 32;
            uint32_t Ah[4][4], Al[4][4], Bh[4][2], Bl[4][2];
            #pragma unroll
            for (int i = 0; i < 4; ++i) {
                ldsm4(Ah[i], aA + SA_HI + i * (16 * ROW_B) + kb);
                ldsm4(Al[i], aA + SA_LO + i * (16 * ROW_B) + kb);
            }
            #pragma unroll
            for (int j = 0; j < 4; ++j) {
                ldsm2(Bh[j], aB + j * (8 * WROW) + kb);
                ldsm2(Bl[j], aB + SW_LO + j * (8 * WROW) + kb);
            }
            #pragma unroll
            for (int i = 0; i < 4; ++i)
                #pragma unroll
                for (int j = 0; j < 4; ++j) {
                    mma_bf16(acc[i][j], Ah[i], Bh[j]);
                    mma_bf16(acc[i][j], Ah[i], Bl[j]);
                    mma_bf16(acc[i][j], Al[i], Bh[j]);
                }
        }
        __syncthreads();   // readers done before ring slot reuse
        if (s < 18) {
            stage_w(sb + SW_BASE + (s & 1) * SW_STG, s + 2, tid);
            asm volatile("cp.async.commit_group;" ::: "memory");
        }
    }

    // ---- epilogue: bias + exact GELU + store ----
    const float* bs = reinterpret_cast<const float*>(smem + SBIAS);
    #pragma unroll
    for (int i = 0; i < 4; ++i) {
        int row0 = s0 + wm * 64 + i * 16 + g;
        #pragma unroll
        for (int j = 0; j < 4; ++j) {
            int col = wn * 32 + j * 8 + q * 2;
            float b0 = bs[col], b1 = bs[col + 1];
            float2 v0, v1;
            v0.x = gelu_exact(acc[i][j][0] + b0);
            v0.y = gelu_exact(acc[i][j][1] + b1);
            v1.x = gelu_exact(acc[i][j][2] + b0);
            v1.y = gelu_exact(acc[i][j][3] + b1);
            float* p0 = out + ((size_t)(batch * CE_S + row0)) * 128 + col;
            *reinterpret_cast<float2*>(p0) = v0;
            *reinterpret_cast<float2*>(p0 + 8 * 128) = v1;
        }
    }
}

extern "C" void kernel_launch(void* const* d_in, const int* in_sizes, int n_in,
                              void* d_out, int out_size)
{
    const int*   x    = (const int*)  d_in[0];
    const float* emb  = (const float*)d_in[1];
    const float* W    = (const float*)d_in[2];
    const float* bias = (const float*)d_in[3];
    float*       out  = (float*)d_out;

    prep_w_kernel<<<40, 256>>>(W);

    cudaFuncSetAttribute(conv_encoder_hmma,
                         cudaFuncAttributeMaxDynamicSharedMemorySize, SM_TOT);
    dim3 grid(CE_S / TOK, 16);   // 16 x 16 = 256 CTAs, 2 per SM
    conv_encoder_hmma<<<grid, THREADS, SM_TOT>>>(x, emb, bias, out);
}

// round 8
// speedup vs baseline: 1.0765x; 1.0765x over previous
#include <cuda_runtime.h>
#include <cuda_bf16.h>
#include <math.h>
#include <stdint.h>

// ConvEncoder: y = GELU(im2col(emb[x]) @ W^T + b).  M=32768, N=128, K=640.
// mma.sync m16n8k16 bf16, split precision: D += AhWh + AhWl + AlWh (~2^-17 err).
// R8: R7 with the phase-2 gather indexing fixed (column base 16, same rows),
// which was writing out of bounds. Half-major K order: prologue gathers A
// cols 0-63; cols 64-127 gathered inside sub-chunks s=0..1 (first use s=5).

#define CE_S    2048
#define CE_KTOT 640
#define THREADS 512
#define TOK     256
#define ROW_B   272                  // A smem row stride (256B data + 16B pad)
#define WROW    144                  // W smem row stride (128B data + 16B pad)

// smem layout (bytes)
#define SA_HI   0
#define SA_LO   70720                // 260 * 272
#define SW_BASE 141440               // 2 bufs x (hi 18432 + lo 18432)
#define SW_BUF  36864
#define SW_LO   18432
#define SBIAS   215168
#define SIDX    215680               // 260 ints
#define SM_TOT  216768

// W pre-converted: [h(2)][kc(5)][o(128)][272B]
__device__ __align__(16) unsigned char g_Wcvt[2 * 5 * 128 * ROW_B];

__device__ __forceinline__ float gelu_exact(float y) {
    return 0.5f * y * (1.0f + erff(y * 0.70710678118654752f));
}

__device__ __forceinline__ void mma_bf16(float* c, const uint32_t* a, const uint32_t* b) {
    asm volatile(
        "mma.sync.aligned.m16n8k16.row.col.f32.bf16.bf16.f32 "
        "{%0,%1,%2,%3}, {%4,%5,%6,%7}, {%8,%9}, {%0,%1,%2,%3};"
        : "+f"(c[0]), "+f"(c[1]), "+f"(c[2]), "+f"(c[3])
        : "r"(a[0]), "r"(a[1]), "r"(a[2]), "r"(a[3]), "r"(b[0]), "r"(b[1]));
}

__device__ __forceinline__ void ldsm4(uint32_t* r, uint32_t addr) {
    asm volatile("ldmatrix.sync.aligned.m8n8.x4.shared.b16 {%0,%1,%2,%3}, [%4];"
                 : "=r"(r[0]), "=r"(r[1]), "=r"(r[2]), "=r"(r[3]) : "r"(addr));
}

__device__ __forceinline__ void ldsm2(uint32_t* r, uint32_t addr) {
    asm volatile("ldmatrix.sync.aligned.m8n8.x2.shared.b16 {%0,%1}, [%2];"
                 : "=r"(r[0]), "=r"(r[1]) : "r"(addr));
}

__device__ __forceinline__ void cpasync16(uint32_t dst, const void* src) {
    asm volatile("cp.async.cg.shared.global [%0], [%1], 16;"
                 :: "r"(dst), "l"(src) : "memory");
}

__device__ __forceinline__ void split4(float4 v, uint2* hi, uint2* lo) {
    union { __nv_bfloat16 h[4]; uint2 u; } ph, pl;
    float f[4] = {v.x, v.y, v.z, v.w};
    #pragma unroll
    for (int j = 0; j < 4; ++j) {
        __nv_bfloat16 hb = __float2bfloat16(f[j]);
        ph.h[j] = hb;
        pl.h[j] = __float2bfloat16(f[j] - __bfloat162float(hb));
    }
    *hi = ph.u;
    *lo = pl.u;
}

// ---- prep: W f32 -> bf16 hi/lo, chunked layout for direct cp.async ----
__global__ void __launch_bounds__(256)
prep_w_kernel(const float* __restrict__ W)
{
    int t = blockIdx.x * 256 + threadIdx.x;        // 5*128*16 = 10240 granules
    if (t >= 5 * 128 * 16) return;
    int gnl = t & 15;
    int o   = (t >> 4) & 127;
    int kc  = t >> 11;
    const float* src = W + (size_t)o * CE_KTOT + kc * 128 + gnl * 8;
    float4 v0 = *reinterpret_cast<const float4*>(src);
    float4 v1 = *reinterpret_cast<const float4*>(src + 4);
    uint2 h0, l0, h1, l1;
    split4(v0, &h0, &l0);
    split4(v1, &h1, &l1);
    size_t off_hi = ((size_t)(0 * 5 + kc) * 128 + o) * ROW_B + gnl * 16;
    size_t off_lo = ((size_t)(1 * 5 + kc) * 128 + o) * ROW_B + gnl * 16;
    *reinterpret_cast<uint4*>(g_Wcvt + off_hi) = make_uint4(h0.x, h0.y, h1.x, h1.y);
    *reinterpret_cast<uint4*>(g_Wcvt + off_lo) = make_uint4(l0.x, l0.y, l1.x, l1.y);
}

// stage one K=64 sub-chunk (hi+lo) into smem buffer via cp.async.
// half-major order: s in [0,10): khalf = s/5, kc = s%5.
__device__ __forceinline__ void stage_w(uint32_t swdst, int s, int tid) {
    const int kc    = s % 5;
    const int khalf = s / 5;
    const unsigned char* bh = g_Wcvt + (size_t)(0 * 5 + kc) * 128 * ROW_B;
    const unsigned char* bl = g_Wcvt + (size_t)(1 * 5 + kc) * 128 * ROW_B;
    #pragma unroll
    for (int it = 0; it < 2; ++it) {
        int idx = tid + it * THREADS;              // 128 o x 8 granules
        int o = idx >> 3, gnl = idx & 7;
        uint32_t d = swdst + o * WROW + gnl * 16;
        size_t so = (size_t)o * ROW_B + khalf * 128 + gnl * 16;
        cpasync16(d, bh + so);
        cpasync16(d + SW_LO, bl + so);
    }
}

// gather + split one A granule: halo row p (0..259), 16B granule c within row,
// cbase selects column half (0 -> cols 0-63, 16 -> cols 64-127).
__device__ __forceinline__ void gather_a(uint8_t* smem, const float* emb,
                                         int idx, int cbase) {
    int p = idx >> 4;                  // halo row 0..259
    int c = cbase + (idx & 15);        // granule 0..31 within full 128-col row
    int tok = reinterpret_cast<const int*>(smem + SIDX)[p];
    float4 v = make_float4(0.f, 0.f, 0.f, 0.f);
    if (tok >= 0)
        v = *reinterpret_cast<const float4*>(emb + (size_t)tok * 128 + c * 4);
    uint2 hi, lo;
    split4(v, &hi, &lo);
    *reinterpret_cast<uint2*>(smem + SA_HI + p * ROW_B + c * 8) = hi;
    *reinterpret_cast<uint2*>(smem + SA_LO + p * ROW_B + c * 8) = lo;
}

__global__ void __launch_bounds__(THREADS, 1)
conv_encoder_hmma(const int* __restrict__ x,
                  const float* __restrict__ emb,
                  const float* __restrict__ bias,
                  float* __restrict__ out)
{
    extern __shared__ uint8_t smem[];
    uint32_t sb;
    asm("{ .reg .u64 t; cvta.to.shared.u64 t, %1; cvt.u32.u64 %0, t; }"
        : "=r"(sb) : "l"(smem));

    const int tid = threadIdx.x;
    const int wid = tid >> 5;
    const int lid = tid & 31;
    const int g   = lid >> 2;
    const int q   = lid & 3;
    const int wm  = wid >> 2;       // 0..3  (64-row band within 256)
    const int wn  = wid & 3;        // 0..3  (32-col band)
    const int batch = blockIdx.y;
    const int s0 = blockIdx.x * TOK;

    // prefetch first two W sub-chunks
    stage_w(sb + SW_BASE, 0, tid);
    asm volatile("cp.async.commit_group;" ::: "memory");
    stage_w(sb + SW_BASE + SW_BUF, 1, tid);
    asm volatile("cp.async.commit_group;" ::: "memory");

    if (tid < 32) {
        reinterpret_cast<float4*>(smem + SBIAS)[tid] =
            reinterpret_cast<const float4*>(bias)[tid];
    }
    // token index cache: halo rows p=0..259 -> seq s0+p-2 (or -1 if OOB)
    if (tid < 260) {
        int s = s0 + tid - 2;
        reinterpret_cast<int*>(smem + SIDX)[tid] =
            (s >= 0 && s < CE_S) ? x[batch * CE_S + s] : -1;
    }
    __syncthreads();

    // ---- phase-1 prologue: A cols 0-63 only (4160 granules) ----
    #pragma unroll
    for (int j = 0; j < 9; ++j) {
        int idx = tid + j * THREADS;
        if (idx < 260 * 16) gather_a(smem, emb, idx, 0);
    }

    float acc[4][4][4];
    #pragma unroll
    for (int i = 0; i < 4; ++i)
        #pragma unroll
        for (int j = 0; j < 4; ++j)
            #pragma unroll
            for (int r = 0; r < 4; ++r)
                acc[i][j][r] = 0.f;

    // per-lane ldmatrix offsets
    const uint32_t a_off = ((lid & 7) + ((lid >> 3) & 1) * 8) * ROW_B + (lid >> 4) * 16;
    const uint32_t b_off = (lid & 7) * WROW + ((lid >> 3) & 1) * 16;

    // ---- 10 sub-chunks of K=64, half-major order, double-buffered W ----
    for (int s = 0; s < 10; ++s) {
        if (s < 9) {
            asm volatile("cp.async.wait_group 1;" ::: "memory");
        } else {
            asm volatile("cp.async.wait_group 0;" ::: "memory");
        }
        __syncthreads();

        // phase-2 A gather (cols 64-127, same rows 0..259), hidden under
        // the first two sub-chunks' MMAs; first use is s=5.
        if (s == 0) {
            #pragma unroll
            for (int j = 0; j < 4; ++j)
                gather_a(smem, emb, tid + j * THREADS, 16);
        } else if (s == 1) {
            #pragma unroll
            for (int j = 4; j < 9; ++j) {
                int idx = tid + j * THREADS;
                if (idx < 260 * 16) gather_a(smem, emb, idx, 16);
            }
        }

        const int kc    = s % 5;
        const int khalf = s / 5;
        const uint32_t swb = sb + SW_BASE + (s & 1) * SW_BUF;
        const uint32_t aA  = sb + (wm * 64 + kc) * ROW_B + a_off + khalf * 128;
        const uint32_t aB  = swb + wn * 32 * WROW + b_off;

        #pragma unroll
        for (int ks = 0; ks < 4; ++ks) {
            const uint32_t kb = ks * 32;
            uint32_t Ah[4][4], Al[4][4], Bh[4][2], Bl[4][2];
            #pragma unroll
            for (int i = 0; i < 4; ++i) {
                ldsm4(Ah[i], aA + SA_HI + i * (16 * ROW_B) + kb);
                ldsm4(Al[i], aA + SA_LO + i * (16 * ROW_B) + kb);
            }
            #pragma unroll
            for (int j = 0; j < 4; ++j) {
                ldsm2(Bh[j], aB + j * (8 * WROW) + kb);
                ldsm2(Bl[j], aB + SW_LO + j * (8 * WROW) + kb);
            }
            #pragma unroll
            for (int i = 0; i < 4; ++i)
                #pragma unroll
                for (int j = 0; j < 4; ++j) {
                    mma_bf16(acc[i][j], Ah[i], Bh[j]);
                    mma_bf16(acc[i][j], Ah[i], Bl[j]);
                    mma_bf16(acc[i][j], Al[i], Bh[j]);
                }
        }
        __syncthreads();   // readers done before buffer reuse
        if (s < 8) {
            stage_w(sb + SW_BASE + (s & 1) * SW_BUF, s + 2, tid);
            asm volatile("cp.async.commit_group;" ::: "memory");
        }
    }

    // ---- epilogue: bias + exact GELU + store ----
    const float* bs = reinterpret_cast<const float*>(smem + SBIAS);
    #pragma unroll
    for (int i = 0; i < 4; ++i) {
        int row0 = s0 + wm * 64 + i * 16 + g;
        #pragma unroll
        for (int j = 0; j < 4; ++j) {
            int col = wn * 32 + j * 8 + q * 2;
            float b0 = bs[col], b1 = bs[col + 1];
            float2 v0, v1;
            v0.x = gelu_exact(acc[i][j][0] + b0);
            v0.y = gelu_exact(acc[i][j][1] + b1);
            v1.x = gelu_exact(acc[i][j][2] + b0);
            v1.y = gelu_exact(acc[i][j][3] + b1);
            float* p0 = out + ((size_t)(batch * CE_S + row0)) * 128 + col;
            *reinterpret_cast<float2*>(p0) = v0;
            *reinterpret_cast<float2*>(p0 + 8 * 128) = v1;
        }
    }
}

extern "C" void kernel_launch(void* const* d_in, const int* in_sizes, int n_in,
                              void* d_out, int out_size)
{
    const int*   x    = (const int*)  d_in[0];
    const float* emb  = (const float*)d_in[1];
    const float* W    = (const float*)d_in[2];
    const float* bias = (const float*)d_in[3];
    float*       out  = (float*)d_out;

    prep_w_kernel<<<40, 256>>>(W);

    cudaFuncSetAttribute(conv_encoder_hmma,
                         cudaFuncAttributeMaxDynamicSharedMemorySize, SM_TOT);
    dim3 grid(CE_S / TOK, 16);   // 8 x 16 = 128 CTAs (one wave)
    conv_encoder_hmma<<<grid, THREADS, SM_TOT>>>(x, emb, bias, out);
}

// round 9
// speedup vs baseline: 1.1107x; 1.0318x over previous
#include <cuda_runtime.h>
#include <cuda_bf16.h>
#include <math.h>
#include <stdint.h>

// ConvEncoder: y = GELU(im2col(emb[x]) @ W^T + b).  M=32768, N=128, K=640.
// mma.sync m16n8k16 bf16, split precision: D += AhWh + AhWl + AlWh (~2^-17 err).
// R9: R5 base (256 tok/CTA, 512 thr, 128 CTAs = 1 wave, K=64 W double buffer)
// + B fragments via j-paired ldmatrix.x4 (25% fewer LDSM issues)
// + token-index smem cache for the A gather.

#define CE_S    2048
#define CE_KTOT 640
#define THREADS 512
#define TOK     256
#define ROW_B   272                  // A smem row stride (256B data + 16B pad)
#define WROW    144                  // W smem row stride (128B data + 16B pad)

// smem layout (bytes)
#define SA_HI   0
#define SA_LO   70720                // 260 * 272
#define SW_BASE 141440               // 2 bufs x (hi 18432 + lo 18432)
#define SW_BUF  36864
#define SW_LO   18432
#define SBIAS   215168
#define SIDX    215680               // 260 ints
#define SM_TOT  216768

// W pre-converted: [h(2)][kc(5)][o(128)][272B]
__device__ __align__(16) unsigned char g_Wcvt[2 * 5 * 128 * ROW_B];

__device__ __forceinline__ float gelu_exact(float y) {
    return 0.5f * y * (1.0f + erff(y * 0.70710678118654752f));
}

__device__ __forceinline__ void mma_bf16(float* c, const uint32_t* a, const uint32_t* b) {
    asm volatile(
        "mma.sync.aligned.m16n8k16.row.col.f32.bf16.bf16.f32 "
        "{%0,%1,%2,%3}, {%4,%5,%6,%7}, {%8,%9}, {%0,%1,%2,%3};"
        : "+f"(c[0]), "+f"(c[1]), "+f"(c[2]), "+f"(c[3])
        : "r"(a[0]), "r"(a[1]), "r"(a[2]), "r"(a[3]), "r"(b[0]), "r"(b[1]));
}

__device__ __forceinline__ void ldsm4(uint32_t* r, uint32_t addr) {
    asm volatile("ldmatrix.sync.aligned.m8n8.x4.shared.b16 {%0,%1,%2,%3}, [%4];"
                 : "=r"(r[0]), "=r"(r[1]), "=r"(r[2]), "=r"(r[3]) : "r"(addr));
}

__device__ __forceinline__ void cpasync16(uint32_t dst, const void* src) {
    asm volatile("cp.async.cg.shared.global [%0], [%1], 16;"
                 :: "r"(dst), "l"(src) : "memory");
}

__device__ __forceinline__ void split4(float4 v, uint2* hi, uint2* lo) {
    union { __nv_bfloat16 h[4]; uint2 u; } ph, pl;
    float f[4] = {v.x, v.y, v.z, v.w};
    #pragma unroll
    for (int j = 0; j < 4; ++j) {
        __nv_bfloat16 hb = __float2bfloat16(f[j]);
        ph.h[j] = hb;
        pl.h[j] = __float2bfloat16(f[j] - __bfloat162float(hb));
    }
    *hi = ph.u;
    *lo = pl.u;
}

// ---- prep: W f32 -> bf16 hi/lo, chunked layout for direct cp.async ----
__global__ void __launch_bounds__(256)
prep_w_kernel(const float* __restrict__ W)
{
    int t = blockIdx.x * 256 + threadIdx.x;        // 5*128*16 = 10240 granules
    if (t >= 5 * 128 * 16) return;
    int gnl = t & 15;
    int o   = (t >> 4) & 127;
    int kc  = t >> 11;
    const float* src = W + (size_t)o * CE_KTOT + kc * 128 + gnl * 8;
    float4 v0 = *reinterpret_cast<const float4*>(src);
    float4 v1 = *reinterpret_cast<const float4*>(src + 4);
    uint2 h0, l0, h1, l1;
    split4(v0, &h0, &l0);
    split4(v1, &h1, &l1);
    size_t off_hi = ((size_t)(0 * 5 + kc) * 128 + o) * ROW_B + gnl * 16;
    size_t off_lo = ((size_t)(1 * 5 + kc) * 128 + o) * ROW_B + gnl * 16;
    *reinterpret_cast<uint4*>(g_Wcvt + off_hi) = make_uint4(h0.x, h0.y, h1.x, h1.y);
    *reinterpret_cast<uint4*>(g_Wcvt + off_lo) = make_uint4(l0.x, l0.y, l1.x, l1.y);
}

// stage one K=64 sub-chunk (hi+lo) into smem buffer via cp.async
__device__ __forceinline__ void stage_w(uint32_t swdst, int sub, int tid) {
    const int kc    = sub >> 1;
    const int khalf = sub & 1;
    const unsigned char* bh = g_Wcvt + (size_t)(0 * 5 + kc) * 128 * ROW_B;
    const unsigned char* bl = g_Wcvt + (size_t)(1 * 5 + kc) * 128 * ROW_B;
    #pragma unroll
    for (int it = 0; it < 2; ++it) {
        int idx = tid + it * THREADS;              // 128 o x 8 granules
        int o = idx >> 3, gnl = idx & 7;
        uint32_t d = swdst + o * WROW + gnl * 16;
        size_t so = (size_t)o * ROW_B + khalf * 128 + gnl * 16;
        cpasync16(d, bh + so);
        cpasync16(d + SW_LO, bl + so);
    }
}

__global__ void __launch_bounds__(THREADS, 1)
conv_encoder_hmma(const int* __restrict__ x,
                  const float* __restrict__ emb,
                  const float* __restrict__ bias,
                  float* __restrict__ out)
{
    extern __shared__ uint8_t smem[];
    uint32_t sb;
    asm("{ .reg .u64 t; cvta.to.shared.u64 t, %1; cvt.u32.u64 %0, t; }"
        : "=r"(sb) : "l"(smem));

    const int tid = threadIdx.x;
    const int wid = tid >> 5;
    const int lid = tid & 31;
    const int g   = lid >> 2;
    const int q   = lid & 3;
    const int wm  = wid >> 2;       // 0..3  (64-row band within 256)
    const int wn  = wid & 3;        // 0..3  (32-col band)
    const int batch = blockIdx.y;
    const int s0 = blockIdx.x * TOK;

    // prefetch first two W sub-chunks (overlap with A gather)
    stage_w(sb + SW_BASE, 0, tid);
    asm volatile("cp.async.commit_group;" ::: "memory");
    stage_w(sb + SW_BASE + SW_BUF, 1, tid);
    asm volatile("cp.async.commit_group;" ::: "memory");

    if (tid < 32) {
        reinterpret_cast<float4*>(smem + SBIAS)[tid] =
            reinterpret_cast<const float4*>(bias)[tid];
    }
    // token index cache: halo rows p=0..259 -> seq s0+p-2 (or -1 if OOB)
    if (tid >= THREADS - 260) {
        int p = tid - (THREADS - 260);
        int s = s0 + p - 2;
        reinterpret_cast<int*>(smem + SIDX)[p] =
            (s >= 0 && s < CE_S) ? x[batch * CE_S + s] : -1;
    }
    __syncthreads();

    // ---- stage halo'd A once: rows p=0..259 -> seq s0+p-2, bf16 hi/lo ----
    #pragma unroll
    for (int it = 0; it < 17; ++it) {
        int idx = tid + it * THREADS;              // 260*32 = 8320 float4 tasks
        if (idx < 260 * 32) {
            int p = idx >> 5;
            int c = idx & 31;
            int tok = reinterpret_cast<const int*>(smem + SIDX)[p];
            float4 v = make_float4(0.f, 0.f, 0.f, 0.f);
            if (tok >= 0)
                v = *reinterpret_cast<const float4*>(emb + (size_t)tok * 128 + c * 4);
            uint2 hi, lo;
            split4(v, &hi, &lo);
            *reinterpret_cast<uint2*>(smem + SA_HI + p * ROW_B + c * 8) = hi;
            *reinterpret_cast<uint2*>(smem + SA_LO + p * ROW_B + c * 8) = lo;
        }
    }

    float acc[4][4][4];
    #pragma unroll
    for (int i = 0; i < 4; ++i)
        #pragma unroll
        for (int j = 0; j < 4; ++j)
            #pragma unroll
            for (int r = 0; r < 4; ++r)
                acc[i][j][r] = 0.f;

    // per-lane ldmatrix offsets
    // A (x4): lanes 0-7 rows 0-7, 8-15 rows 8-15, 16-31 k-halves
    const uint32_t a_off = ((lid & 7) + ((lid >> 3) & 1) * 8) * ROW_B + (lid >> 4) * 16;
    // B (x4, j-paired): lanes 0-15 -> n-tile j (k halves), 16-31 -> n-tile j+1
    const uint32_t b_off = ((lid & 7) + (lid >> 4) * 8) * WROW + ((lid >> 3) & 1) * 16;

    // ---- 10 sub-chunks of K=64, double-buffered ----
    for (int s = 0; s < 10; ++s) {
        if (s < 9) {
            asm volatile("cp.async.wait_group 1;" ::: "memory");
        } else {
            asm volatile("cp.async.wait_group 0;" ::: "memory");
        }
        __syncthreads();

        const int kc    = s >> 1;
        const uint32_t kbase = (uint32_t)((s & 1) * 128);
        const uint32_t swb = sb + SW_BASE + (s & 1) * SW_BUF;
        const uint32_t aA  = sb + (wm * 64 + kc) * ROW_B + a_off + kbase;
        const uint32_t aB  = swb + wn * 32 * WROW + b_off;

        #pragma unroll
        for (int ks = 0; ks < 4; ++ks) {
            const uint32_t kb = ks * 32;
            uint32_t Ah[4][4], Al[4][4], Bh[2][4], Bl[2][4];
            #pragma unroll
            for (int i = 0; i < 4; ++i) {
                ldsm4(Ah[i], aA + SA_HI + i * (16 * ROW_B) + kb);
                ldsm4(Al[i], aA + SA_LO + i * (16 * ROW_B) + kb);
            }
            #pragma unroll
            for (int jp = 0; jp < 2; ++jp) {
                ldsm4(Bh[jp], aB + jp * (16 * WROW) + kb);
                ldsm4(Bl[jp], aB + SW_LO + jp * (16 * WROW) + kb);
            }
            #pragma unroll
            for (int i = 0; i < 4; ++i)
                #pragma unroll
                for (int j = 0; j < 4; ++j) {
                    const uint32_t* bh = &Bh[j >> 1][(j & 1) * 2];
                    const uint32_t* bl = &Bl[j >> 1][(j & 1) * 2];
                    mma_bf16(acc[i][j], Ah[i], bh);
                    mma_bf16(acc[i][j], Ah[i], bl);
                    mma_bf16(acc[i][j], Al[i], bh);
                }
        }
        __syncthreads();   // readers done before buffer reuse
        if (s < 8) {
            stage_w(sb + SW_BASE + (s & 1) * SW_BUF, s + 2, tid);
            asm volatile("cp.async.commit_group;" ::: "memory");
        }
    }

    // ---- epilogue: bias + exact GELU + store ----
    const float* bs = reinterpret_cast<const float*>(smem + SBIAS);
    #pragma unroll
    for (int i = 0; i < 4; ++i) {
        int row0 = s0 + wm * 64 + i * 16 + g;
        #pragma unroll
        for (int j = 0; j < 4; ++j) {
            int col = wn * 32 + j * 8 + q * 2;
            float b0 = bs[col], b1 = bs[col + 1];
            float2 v0, v1;
            v0.x = gelu_exact(acc[i][j][0] + b0);
            v0.y = gelu_exact(acc[i][j][1] + b1);
            v1.x = gelu_exact(acc[i][j][2] + b0);
            v1.y = gelu_exact(acc[i][j][3] + b1);
            float* p0 = out + ((size_t)(batch * CE_S + row0)) * 128 + col;
            *reinterpret_cast<float2*>(p0) = v0;
            *reinterpret_cast<float2*>(p0 + 8 * 128) = v1;
        }
    }
}

extern "C" void kernel_launch(void* const* d_in, const int* in_sizes, int n_in,
                              void* d_out, int out_size)
{
    const int*   x    = (const int*)  d_in[0];
    const float* emb  = (const float*)d_in[1];
    const float* W    = (const float*)d_in[2];
    const float* bias = (const float*)d_in[3];
    float*       out  = (float*)d_out;

    prep_w_kernel<<<40, 256>>>(W);

    cudaFuncSetAttribute(conv_encoder_hmma,
                         cudaFuncAttributeMaxDynamicSharedMemorySize, SM_TOT);
    dim3 grid(CE_S / TOK, 16);   // 8 x 16 = 128 CTAs (one wave)
    conv_encoder_hmma<<<grid, THREADS, SM_TOT>>>(x, emb, bias, out);
}

// round 10
// speedup vs baseline: 2.3193x; 2.0881x over previous
#include <cuda_runtime.h>
#include <cuda_fp16.h>
#include <math.h>
#include <stdint.h>

// ConvEncoder: y = GELU(im2col(emb[x]) @ W^T + b).  M=32768, N=128, K=640.
// R10: SINGLE-PASS fp16 mma.sync m16n8k16 (error ~3e-4 << 1e-3 budget),
// 3x less tensor work than the bf16-split scheme. W streamed as 5 K=128
// chunks through a 3-slot cp.async ring -> one __syncthreads per chunk.
// Geometry: 256 tok/CTA, 512 thr, 128 CTAs = 1 wave.

#define CE_S    2048
#define CE_KTOT 640
#define THREADS 512
#define TOK     256
#define ROW_B   272                  // fp16 row: 256B data + 16B pad (A and W)

// smem layout (bytes)
#define SA      0                    // 260 rows * 272
#define SW_BASE 70720                // 3 slots x 34816 (128 rows * 272)
#define SW_SLOT 34816
#define SBIAS   175168
#define SIDX    175680               // 260 ints
#define SM_TOT  176768

// W pre-converted fp16: [kc(5)][o(128)][272B]
__device__ __align__(16) unsigned char g_Wcvt[5 * 128 * ROW_B];

__device__ __forceinline__ float gelu_exact(float y) {
    return 0.5f * y * (1.0f + erff(y * 0.70710678118654752f));
}

__device__ __forceinline__ void mma_f16(float* c, const uint32_t* a, const uint32_t* b) {
    asm volatile(
        "mma.sync.aligned.m16n8k16.row.col.f32.f16.f16.f32 "
        "{%0,%1,%2,%3}, {%4,%5,%6,%7}, {%8,%9}, {%0,%1,%2,%3};"
        : "+f"(c[0]), "+f"(c[1]), "+f"(c[2]), "+f"(c[3])
        : "r"(a[0]), "r"(a[1]), "r"(a[2]), "r"(a[3]), "r"(b[0]), "r"(b[1]));
}

__device__ __forceinline__ void ldsm4(uint32_t* r, uint32_t addr) {
    asm volatile("ldmatrix.sync.aligned.m8n8.x4.shared.b16 {%0,%1,%2,%3}, [%4];"
                 : "=r"(r[0]), "=r"(r[1]), "=r"(r[2]), "=r"(r[3]) : "r"(addr));
}

__device__ __forceinline__ void cpasync16(uint32_t dst, const void* src) {
    asm volatile("cp.async.cg.shared.global [%0], [%1], 16;"
                 :: "r"(dst), "l"(src) : "memory");
}

// convert 8 f32 -> 8 fp16 packed as uint4 (16 bytes)
__device__ __forceinline__ uint4 cvt8_f16(float4 v0, float4 v1) {
    union { __half2 h[4]; uint4 u; } p;
    p.h[0] = __float22half2_rn(make_float2(v0.x, v0.y));
    p.h[1] = __float22half2_rn(make_float2(v0.z, v0.w));
    p.h[2] = __float22half2_rn(make_float2(v1.x, v1.y));
    p.h[3] = __float22half2_rn(make_float2(v1.z, v1.w));
    return p.u;
}

// ---- prep: W f32 -> fp16, chunked layout for direct cp.async ----
__global__ void __launch_bounds__(256)
prep_w_kernel(const float* __restrict__ W)
{
    int t = blockIdx.x * 256 + threadIdx.x;        // 5*128*16 = 10240 granules
    if (t >= 5 * 128 * 16) return;
    int gnl = t & 15;
    int o   = (t >> 4) & 127;
    int kc  = t >> 11;
    const float* src = W + (size_t)o * CE_KTOT + kc * 128 + gnl * 8;
    float4 v0 = *reinterpret_cast<const float4*>(src);
    float4 v1 = *reinterpret_cast<const float4*>(src + 4);
    *reinterpret_cast<uint4*>(g_Wcvt + ((size_t)kc * 128 + o) * ROW_B + gnl * 16)
        = cvt8_f16(v0, v1);
}

// stage one K=128 W chunk into a smem ring slot via cp.async
__device__ __forceinline__ void stage_w(uint32_t swdst, int kc, int tid) {
    const unsigned char* base = g_Wcvt + (size_t)kc * 128 * ROW_B;
    #pragma unroll
    for (int it = 0; it < 4; ++it) {
        int idx = tid + it * THREADS;              // 2048: 128 o x 16 granules
        int o = idx >> 4, gnl = idx & 15;
        cpasync16(swdst + o * ROW_B + gnl * 16,
                  base + (size_t)o * ROW_B + gnl * 16);
    }
}

__global__ void __launch_bounds__(THREADS, 1)
conv_encoder_hmma(const int* __restrict__ x,
                  const float* __restrict__ emb,
                  const float* __restrict__ bias,
                  float* __restrict__ out)
{
    extern __shared__ uint8_t smem[];
    uint32_t sb;
    asm("{ .reg .u64 t; cvta.to.shared.u64 t, %1; cvt.u32.u64 %0, t; }"
        : "=r"(sb) : "l"(smem));

    const int tid = threadIdx.x;
    const int wid = tid >> 5;
    const int lid = tid & 31;
    const int g   = lid >> 2;
    const int q   = lid & 3;
    const int wm  = wid >> 2;       // 0..3  (64-row band within 256)
    const int wn  = wid & 3;        // 0..3  (32-col band)
    const int batch = blockIdx.y;
    const int s0 = blockIdx.x * TOK;

    // prefetch W chunks 0 and 1 (overlaps the A gather)
    stage_w(sb + SW_BASE, 0, tid);
    asm volatile("cp.async.commit_group;" ::: "memory");
    stage_w(sb + SW_BASE + SW_SLOT, 1, tid);
    asm volatile("cp.async.commit_group;" ::: "memory");

    if (tid < 32) {
        reinterpret_cast<float4*>(smem + SBIAS)[tid] =
            reinterpret_cast<const float4*>(bias)[tid];
    }
    // token index cache: halo rows p=0..259 -> seq s0+p-2 (or -1 if OOB)
    if (tid >= THREADS - 260) {
        int p = tid - (THREADS - 260);
        int s = s0 + p - 2;
        reinterpret_cast<int*>(smem + SIDX)[p] =
            (s >= 0 && s < CE_S) ? x[batch * CE_S + s] : -1;
    }
    __syncthreads();

    // ---- stage halo'd A once: rows p=0..259, fp16 ----
    #pragma unroll
    for (int it = 0; it < 9; ++it) {
        int idx = tid + it * THREADS;              // 260*16 = 4160 tasks (32B each)
        if (idx < 260 * 16) {
            int p = idx >> 4;
            int c = idx & 15;                      // 16B fp16 granule = 8 elems
            int tok = reinterpret_cast<const int*>(smem + SIDX)[p];
            float4 v0 = make_float4(0.f, 0.f, 0.f, 0.f);
            float4 v1 = v0;
            if (tok >= 0) {
                const float* e = emb + (size_t)tok * 128 + c * 8;
                v0 = *reinterpret_cast<const float4*>(e);
                v1 = *reinterpret_cast<const float4*>(e + 4);
            }
            *reinterpret_cast<uint4*>(smem + SA + p * ROW_B + c * 16) = cvt8_f16(v0, v1);
        }
    }

    float acc[4][4][4];
    #pragma unroll
    for (int i = 0; i < 4; ++i)
        #pragma unroll
        for (int j = 0; j < 4; ++j)
            #pragma unroll
            for (int r = 0; r < 4; ++r)
                acc[i][j][r] = 0.f;

    // per-lane ldmatrix offsets
    const uint32_t a_off = ((lid & 7) + ((lid >> 3) & 1) * 8) * ROW_B + (lid >> 4) * 16;
    // B (x4, j-paired): lanes 0-15 -> n-tile j (k halves), 16-31 -> n-tile j+1
    const uint32_t b_off = ((lid & 7) + (lid >> 4) * 8) * ROW_B + ((lid >> 3) & 1) * 16;

    // ---- 5 chunks of K=128, 3-slot ring, ONE sync per chunk ----
    const int slot_of[5] = {0, 1, 2, 0, 1};
    for (int s = 0; s < 5; ++s) {
        __syncthreads();   // all warps done reading chunk s-1 (slot (s+2)%3)
        if (s < 3) {
            stage_w(sb + SW_BASE + slot_of[(s + 2) % 5] * SW_SLOT + ((s + 2) % 3 - slot_of[(s + 2) % 5]) * 0, (s + 2), tid);
            asm volatile("cp.async.commit_group;" ::: "memory");
            asm volatile("cp.async.wait_group 2;" ::: "memory");
        } else if (s == 3) {
            asm volatile("cp.async.wait_group 1;" ::: "memory");
        } else {
            asm volatile("cp.async.wait_group 0;" ::: "memory");
        }
        asm volatile("bar.sync 1, %0;" :: "n"(THREADS) : "memory"); // data visible to all

        const uint32_t swb = sb + SW_BASE + slot_of[s] * SW_SLOT;
        const uint32_t aA  = sb + SA + (wm * 64 + s) * ROW_B + a_off;
        const uint32_t aB  = swb + wn * 32 * ROW_B + b_off;

        #pragma unroll
        for (int ks = 0; ks < 8; ++ks) {
            const uint32_t kb = ks * 32;
            uint32_t Ah[4][4], Bp[2][4];
            #pragma unroll
            for (int i = 0; i < 4; ++i)
                ldsm4(Ah[i], aA + i * (16 * ROW_B) + kb);
            #pragma unroll
            for (int jp = 0; jp < 2; ++jp)
                ldsm4(Bp[jp], aB + jp * (16 * ROW_B) + kb);
            #pragma unroll
            for (int i = 0; i < 4; ++i)
                #pragma unroll
                for (int j = 0; j < 4; ++j)
                    mma_f16(acc[i][j], Ah[i], &Bp[j >> 1][(j & 1) * 2]);
        }
    }

    // ---- epilogue: bias + exact GELU + store ----
    const float* bs = reinterpret_cast<const float*>(smem + SBIAS);
    #pragma unroll
    for (int i = 0; i < 4; ++i) {
        int row0 = s0 + wm * 64 + i * 16 + g;
        #pragma unroll
        for (int j = 0; j < 4; ++j) {
            int col = wn * 32 + j * 8 + q * 2;
            float b0 = bs[col], b1 = bs[col + 1];
            float2 v0, v1;
            v0.x = gelu_exact(acc[i][j][0] + b0);
            v0.y = gelu_exact(acc[i][j][1] + b1);
            v1.x = gelu_exact(acc[i][j][2] + b0);
            v1.y = gelu_exact(acc[i][j][3] + b1);
            float* p0 = out + ((size_t)(batch * CE_S + row0)) * 128 + col;
            *reinterpret_cast<float2*>(p0) = v0;
            *reinterpret_cast<float2*>(p0 + 8 * 128) = v1;
        }
    }
}

extern "C" void kernel_launch(void* const* d_in, const int* in_sizes, int n_in,
                              void* d_out, int out_size)
{
    const int*   x    = (const int*)  d_in[0];
    const float* emb  = (const float*)d_in[1];
    const float* W    = (const float*)d_in[2];
    const float* bias = (const float*)d_in[3];
    float*       out  = (float*)d_out;

    prep_w_kernel<<<40, 256>>>(W);

    cudaFuncSetAttribute(conv_encoder_hmma,
                         cudaFuncAttributeMaxDynamicSharedMemorySize, SM_TOT);
    dim3 grid(CE_S / TOK, 16);   // 8 x 16 = 128 CTAs (one wave)
    conv_encoder_hmma<<<grid, THREADS, SM_TOT>>>(x, emb, bias, out);
}